// round 10
// baseline (speedup 1.0000x reference)
#include <cuda_runtime.h>

#define B_   128
#define S_   512
#define D_   256
#define H_   512
#define ODIM 1275

typedef unsigned long long u64;
typedef unsigned int u32;

// ---------------- persistent device scratch ----------------
__device__ __align__(16) u32 g_x16[S_ * D_ * 64];         // [t][d][bpair] f16x2
__device__ __align__(16) u32 g_h0b[2][H_ * 64];           // [buf][j][bpair] f16x2
__device__ __align__(16) u32 g_h1b[2][H_ * 64];
__device__ __align__(16) float g_W0p[128 * 768 * 16];     // [jtile][k][c], c = jj*4+gate
__device__ __align__(16) float g_W1p[128 * 1024 * 16];
__device__ unsigned g_flags[128 * 32];                    // per-CTA barrier slot, 128B apart

// ---------------- f32x2 / f16 / fast-math helpers ----------------
__device__ __forceinline__ u64 pk2(float x, float y) {
    u64 r; asm("mov.b64 %0, {%1, %2};" : "=l"(r) : "f"(x), "f"(y)); return r;
}
__device__ __forceinline__ float2 up2(u64 v) {
    float2 r; asm("mov.b64 {%0, %1}, %2;" : "=f"(r.x), "=f"(r.y) : "l"(v)); return r;
}
__device__ __forceinline__ u64 add2(u64 a, u64 b) {
    u64 r; asm("add.rn.f32x2 %0, %1, %2;" : "=l"(r) : "l"(a), "l"(b)); return r;
}
#define FMA2(acc, a, b) asm("fma.rn.f32x2 %0, %1, %2, %0;" : "+l"(acc) : "l"(a), "l"(b))

// f16x2 (lo=elem0, hi=elem1) -> f32x2 u64 (lo word = f32 of elem0)
__device__ __forceinline__ u64 hf2f2(u32 v) {
    u64 r;
    asm("{\n\t.reg .f16 a, b;\n\t.reg .b32 lo, hi;\n\t"
        "mov.b32 {a, b}, %1;\n\t"
        "cvt.f32.f16 lo, a;\n\t"
        "cvt.f32.f16 hi, b;\n\t"
        "mov.b64 %0, {lo, hi};\n\t}"
        : "=l"(r) : "r"(v));
    return r;
}
// pack (lo=a, hi=b) as f16x2 round-to-nearest
__device__ __forceinline__ u32 packhf(float a, float b) {
    u32 r; asm("cvt.rn.satfinite.f16x2.f32 %0, %1, %2;" : "=r"(r) : "f"(b), "f"(a));
    return r;
}
__device__ __forceinline__ float hf_lo(u32 v) {
    float f; asm("{\n\t.reg .f16 a, b;\n\tmov.b32 {a, b}, %1;\n\tcvt.f32.f16 %0, a;\n\t}" : "=f"(f) : "r"(v));
    return f;
}
__device__ __forceinline__ float hf_hi(u32 v) {
    float f; asm("{\n\t.reg .f16 a, b;\n\tmov.b32 {a, b}, %1;\n\tcvt.f32.f16 %0, b;\n\t}" : "=f"(f) : "r"(v));
    return f;
}

__device__ __forceinline__ float ex2f(float x) {
    float y; asm("ex2.approx.ftz.f32 %0, %1;" : "=f"(y) : "f"(x)); return y;
}
__device__ __forceinline__ float rcpf(float x) {
    float y; asm("rcp.approx.ftz.f32 %0, %1;" : "=f"(y) : "f"(x)); return y;
}
__device__ __forceinline__ float fsig(float z) {
    return rcpf(1.f + ex2f(-1.44269504088896f * z));
}
__device__ __forceinline__ float ftanh(float z) {
    return 1.f - 2.f * rcpf(1.f + ex2f(2.88539008177793f * z));
}

// ---------------- cp.async ----------------
__device__ __forceinline__ void cp16(float4* dst, const float4* src) {
    unsigned d = (unsigned)__cvta_generic_to_shared(dst);
    asm volatile("cp.async.cg.shared.global [%0], [%1], 16;\n" :: "r"(d), "l"(src));
}
__device__ __forceinline__ void cp_commit() { asm volatile("cp.async.commit_group;\n" ::); }
__device__ __forceinline__ void cp_wait0()  { asm volatile("cp.async.wait_group 0;\n" ::); }

// ---------------- grid-wide barrier: per-CTA flag slots ----------
__device__ __forceinline__ void grid_sync_flag(int jt, int tid, unsigned gen) {
    __syncthreads();
    if (tid == 0) {
        __threadfence();
        *((volatile unsigned*)&g_flags[jt * 32]) = gen;
    }
    if (tid < 128) {
        while (*((volatile unsigned*)&g_flags[tid * 32]) < gen) { }
    }
    __threadfence();
    __syncthreads();
}

// ---------------- prep: transpose+f16 x, pack weights per jtile ----------------
__global__ void prep_kernel(const float* __restrict__ x,
                            const float* __restrict__ W0,
                            const float* __restrict__ W1)
{
    const int stride = gridDim.x * blockDim.x;
    const int tid0 = blockIdx.x * blockDim.x + threadIdx.x;

    if (tid0 < 128 * 32) g_flags[tid0] = 0u;

    // x16[t][d][bp] = f16x2(x[2bp][t][d], x[2bp+1][t][d])
    for (int idx = tid0; idx < S_ * D_ * 64; idx += stride) {
        int t  = idx / (D_ * 64);
        int d  = (idx / 64) % D_;
        int bp = idx & 63;
        float a = x[((2 * bp) * S_ + t) * D_ + d];
        float b = x[((2 * bp + 1) * S_ + t) * D_ + d];
        g_x16[idx] = packhf(a, b);
    }
    for (int idx = tid0; idx < 128 * 768 * 16; idx += stride) {
        int jt = idx / (768 * 16);
        int k  = (idx >> 4) % 768;
        int c  = idx & 15;
        g_W0p[idx] = W0[k * 2048 + (c & 3) * 512 + jt * 4 + (c >> 2)];
    }
    for (int idx = tid0; idx < 128 * 1024 * 16; idx += stride) {
        int jt = idx / (1024 * 16);
        int k  = (idx >> 4) % 1024;
        int c  = idx & 15;
        g_W1p[idx] = W1[k * 2048 + (c & 3) * 512 + jt * 4 + (c >> 2)];
    }
}

// ---------------- activation chunk prefetch (64 k-rows x 128 b f16 = 16KB) ----
// Linear dst, lane-contiguous src: full 128B sectors. 1024 float4 per chunk.
__device__ __forceinline__ void prefetch_chunk(
    float4* s_act4, const float4* srcA, const float4* srcB, bool zeroB,
    int ch, int xch, int tid)
{
    float4* dst = s_act4 + ((ch & 1) << 10);
    if (ch < xch) {
        const float4* s = srcA + ((size_t)ch << 10);
        #pragma unroll
        for (int i = 0; i < 4; i++) { int idx = tid + (i << 8); cp16(dst + idx, s + idx); }
    } else if (zeroB) {
        float4 zz = make_float4(0.f, 0.f, 0.f, 0.f);
        #pragma unroll
        for (int i = 0; i < 4; i++) { int idx = tid + (i << 8); dst[idx] = zz; }
    } else {
        const float4* s = srcB + ((size_t)(ch - xch) << 10);
        #pragma unroll
        for (int i = 0; i < 4; i++) { int idx = tid + (i << 8); cp16(dst + idx, s + idx); }
    }
}

// ---------------- fused GEMM (f16 act, f32 FFMA2, K-split 4) + gates ----------
// 256 threads = 4 ksplit x (16 bt x 4 ct). Thread owns batches 8bt..8bt+7
// (one 16B f16 row segment) x 4 gates of unit j0+ct.
// acc[q*4+g]: q -> batch pair (8bt+2q, 8bt+2q+1), g -> gate.
__device__ __forceinline__ void do_phase(
    const float4* __restrict__ srcA, const float4* __restrict__ srcB, bool zeroB,
    int nch, int xch, bool pf0,
    const float4* __restrict__ s_w4,
    float4* s_act4, u64* s_ps, float* cstate, u32* __restrict__ hout,
    float4 bias4,
    int tid, int ks, int r, int bt, int ct, int j0)
{
    u64 acc[16];
    #pragma unroll
    for (int i = 0; i < 16; i++) acc[i] = 0ull;

    if (pf0) {
        prefetch_chunk(s_act4, srcA, srcB, zeroB, 0, xch, tid);
        cp_commit();
    }

    for (int ch = 0; ch < nch; ch++) {
        cp_wait0();
        __syncthreads();
        if (ch + 1 < nch) {
            prefetch_chunk(s_act4, srcA, srcB, zeroB, ch + 1, xch, tid);
            cp_commit();
        }
        const float4* ab = s_act4 + ((ch & 1) << 10);
        const float4* wt = s_w4 + (ch << 8);

        // software pipeline over 16 k-steps (k = 4u + ks); act row = 16 float4
        float4 A = ab[(ks << 4) + bt];
        float4 W = wt[(ks << 2) + ct];
        #pragma unroll
        for (int u = 0; u < 16; u++) {
            float4 B, V;
            if (u < 15) {
                const int kn = ((u + 1) << 2) | ks;
                B = ab[(kn << 4) + bt];
                V = wt[(kn << 2) + ct];
            }
            u64 p0 = hf2f2(__float_as_uint(A.x));
            u64 p1 = hf2f2(__float_as_uint(A.y));
            u64 p2 = hf2f2(__float_as_uint(A.z));
            u64 p3 = hf2f2(__float_as_uint(A.w));
            u64 s0 = pk2(W.x, W.x), s1 = pk2(W.y, W.y);
            u64 s2 = pk2(W.z, W.z), s3 = pk2(W.w, W.w);
            FMA2(acc[0],  p0, s0); FMA2(acc[1],  p0, s1); FMA2(acc[2],  p0, s2); FMA2(acc[3],  p0, s3);
            FMA2(acc[4],  p1, s0); FMA2(acc[5],  p1, s1); FMA2(acc[6],  p1, s2); FMA2(acc[7],  p1, s3);
            FMA2(acc[8],  p2, s0); FMA2(acc[9],  p2, s1); FMA2(acc[10], p2, s2); FMA2(acc[11], p2, s3);
            FMA2(acc[12], p3, s0); FMA2(acc[13], p3, s1); FMA2(acc[14], p3, s2); FMA2(acc[15], p3, s3);
            A = B; W = V;
        }
    }

    // ---- exchange partials: ps[q][wks][g][r], r innermost -> conflict-free ----
    #pragma unroll
    for (int q = 0; q < 4; q++) {
        if (q != ks) {
            #pragma unroll
            for (int g = 0; g < 4; g++)
                s_ps[(((q << 2) + ks) << 2 | g) * 64 + r] = acc[(q << 2) + g];
        }
    }
    __syncthreads();

    // ---- reduce own quarter (q = ks) + gate math: 2 batches x 4 gates ----
    {
        u64 z[4];
        #pragma unroll
        for (int g = 0; g < 4; g++) z[g] = acc[(ks << 2) + g];
        #pragma unroll
        for (int wks = 0; wks < 4; wks++) {
            if (wks != ks) {
                #pragma unroll
                for (int g = 0; g < 4; g++)
                    z[g] = add2(z[g], s_ps[(((ks << 2) + wks) << 2 | g) * 64 + r]);
            }
        }

        const int j = j0 + ct;
        // after reduction this thread owns batch pair (8bt + 2ks, 8bt + 2ks + 1)
        const int b0 = (bt << 3) + (ks << 1);
        float2 zi = up2(z[0]), zf = up2(z[1]), zg = up2(z[2]), zo = up2(z[3]);

        float* cs = cstate + ct * 128 + b0;
        float2 c = *(float2*)cs;

        float siA = fsig(zi.x + bias4.x), sfA = fsig(zf.x + bias4.y);
        float tgA = ftanh(zg.x + bias4.z), soA = fsig(zo.x + bias4.w);
        float cnA = sfA * c.x + siA * tgA;
        float hA = soA * ftanh(cnA);

        float siB = fsig(zi.y + bias4.x), sfB = fsig(zf.y + bias4.y);
        float tgB = ftanh(zg.y + bias4.z), soB = fsig(zo.y + bias4.w);
        float cnB = sfB * c.y + siB * tgB;
        float hB = soB * ftanh(cnB);

        *(float2*)cs = make_float2(cnA, cnB);
        hout[j * 64 + (b0 >> 1)] = packhf(hA, hB);   // f16x2, lo = batch b0
    }
    __syncthreads();   // ps reads done before next phase's writes
}

// ---------------- persistent main kernel: 128 CTAs x 256 threads ----------------
__global__ void __launch_bounds__(256, 1)
lstm_main(const float* __restrict__ b0g,
          const float* __restrict__ b1g,
          const float* __restrict__ Wp,
          const float* __restrict__ bp,
          float* __restrict__ out)
{
    extern __shared__ float smem[];
    float* s_w0  = smem;                    // 768*16   = 12288 floats
    float* s_w1  = s_w0 + 768 * 16;         // 1024*16  = 16384 floats
    float* s_act = s_w1 + 1024 * 16;        // 2*1024 float4 = 8192 floats
    float* s_psf = s_act + 8192;            // 4096 u64 = 8192 floats
    float* s_c0  = s_psf + 8192;            // 512
    float* s_c1  = s_c0 + 512;              // 512
    // total = 46080 floats = 184320 bytes

    const int tid = threadIdx.x;
    const int jt = blockIdx.x;
    const int j0 = jt * 4;
    const int ks = tid >> 6;      // 0..3
    const int r  = tid & 63;
    const int bt = r >> 2;        // 0..15
    const int ct = r & 3;         // 0..3

    // preload packed weights into smem (resident for entire kernel)
    {
        const float4* w0s = (const float4*)g_W0p + (size_t)jt * 768 * 4;
        const float4* w1s = (const float4*)g_W1p + (size_t)jt * 1024 * 4;
        float4* d0 = (float4*)s_w0;
        float4* d1 = (float4*)s_w1;
        for (int i = tid; i < 768 * 4; i += 256) d0[i] = w0s[i];
        for (int i = tid; i < 1024 * 4; i += 256) d1[i] = w1s[i];
    }
    for (int i = tid; i < 512; i += 256) { s_c0[i] = 0.f; s_c1[i] = 0.f; }
    __syncthreads();

    const int jb = j0 + ct;
    const float4 bias0 = make_float4(b0g[jb], b0g[H_ + jb], b0g[2 * H_ + jb], b0g[3 * H_ + jb]);
    const float4 bias1 = make_float4(b1g[jb], b1g[H_ + jb], b1g[2 * H_ + jb], b1g[3 * H_ + jb]);

    float4* s_act4 = (float4*)s_act;
    u64*    s_ps   = (u64*)s_psf;
    const float4* s_w04 = (const float4*)s_w0;
    const float4* s_w14 = (const float4*)s_w1;

    for (int t = 0; t < S_; t++) {
        const int cur = t & 1, prv = cur ^ 1;

        // L0: act = [x_t (256 rows) | h0_prev (512 rows)], 12 chunks (4 from x).
        // For t>0, chunk 0 (x) was prefetched during the previous step's L1 epilogue.
        do_phase((const float4*)(g_x16 + (size_t)t * D_ * 64),
                 (const float4*)g_h0b[prv], t == 0, 12, 4, /*pf0=*/(t == 0),
                 s_w04, s_act4, s_ps, s_c0, g_h0b[cur], bias0,
                 tid, ks, r, bt, ct, j0);

        grid_sync_flag(jt, tid, (unsigned)(t + 1));   // h0(t) + h1(t-1) visible everywhere

        // L1: act = [h0_cur (512) | h1_prev (512)], 16 chunks (8 from h0)
        do_phase((const float4*)g_h0b[cur],
                 (const float4*)g_h1b[prv], t == 0, 16, 8, /*pf0=*/true,
                 s_w14, s_act4, s_ps, s_c1, g_h1b[cur], bias1,
                 tid, ks, r, bt, ct, j0);

        // early prefetch of next step's x chunk 0 (input-only, no hazard)
        if (t + 1 < S_) {
            prefetch_chunk(s_act4, (const float4*)(g_x16 + (size_t)(t + 1) * D_ * 64),
                           (const float4*)g_h0b[cur], false, 0, 4, tid);
            cp_commit();
        }
    }

    grid_sync_flag(jt, tid, (unsigned)(S_ + 1));

    // ---- projection: out[b][m] = sum_k h1[k][b] * Wp[k][m] + bp[m] ----
    {
        const u32* h1f = g_h1b[1];    // t = 511 -> cur = 1
        int mstart = jt * 10;
        int mend = mstart + 10; if (mend > ODIM) mend = ODIM;
        int b  = tid & 127;
        int mq = tid >> 7;            // 0..1
        const int bp2 = b >> 1;
        const bool hi = (b & 1) != 0;
        for (int m = mstart + mq; m < mend; m += 2) {
            float acc = bp[m];
            #pragma unroll 4
            for (int k = 0; k < H_; k += 2) {
                u32 v0 = h1f[(k + 0) * 64 + bp2];
                u32 v1 = h1f[(k + 1) * 64 + bp2];
                float h0v = hi ? hf_hi(v0) : hf_lo(v0);
                float h1v = hi ? hf_hi(v1) : hf_lo(v1);
                acc += h0v * Wp[(k + 0) * ODIM + m];
                acc += h1v * Wp[(k + 1) * ODIM + m];
            }
            out[b * ODIM + m] = acc;
        }
    }
}

// ---------------- entry ----------------
extern "C" void kernel_launch(void* const* d_in, const int* in_sizes, int n_in,
                              void* d_out, int out_size)
{
    const float* x  = (const float*)d_in[0];
    const float* W0 = (const float*)d_in[1];
    const float* b0 = (const float*)d_in[2];
    const float* W1 = (const float*)d_in[3];
    const float* b1 = (const float*)d_in[4];
    const float* Wp = (const float*)d_in[5];
    const float* bp = (const float*)d_in[6];
    float* out = (float*)d_out;

    cudaFuncSetAttribute(lstm_main, cudaFuncAttributeMaxDynamicSharedMemorySize, 184320);

    prep_kernel<<<2048, 256>>>(x, W0, W1);
    lstm_main<<<128, 256, 184320>>>(b0, b1, Wp, bp, out);
}

// round 12
// speedup vs baseline: 2.9577x; 2.9577x over previous
#include <cuda_runtime.h>
#include <cuda_fp16.h>

#define B_   128
#define S_   512
#define D_   256
#define H_   512
#define ODIM 1275
#define NCTA 64

typedef unsigned long long u64;
typedef unsigned int u32;

// ---------------- persistent device scratch (pre-swizzled f16 tiles) ----------
// tile = [rows][128 k] f16 dense 256B rows; 16B chunk c of row r stored at
// chunk position c ^ (r & 7)  ->  conflict-free ldmatrix, linear cp.async.
__device__ __align__(256) unsigned char g_xs[S_][2][32768];    // x: [t][ch] 128b x 128d
__device__ __align__(256) unsigned char g_h0s[2][4][32768];    // h0: [buf][ch] 128b x 128j
__device__ __align__(256) unsigned char g_h1s[2][4][32768];
__device__ __align__(256) unsigned char g_W0s[NCTA][6][8192];  // [jt][ch] 32n x 128k
__device__ __align__(256) unsigned char g_W1s[NCTA][8][8192];
__device__ unsigned g_flags[NCTA * 32];

// ---------------- helpers ----------------
__device__ __forceinline__ u32 smem_u32(const void* p) {
    u32 a; asm("{ .reg .u64 t; cvta.to.shared.u64 t, %1; cvt.u32.u64 %0, t; }" : "=r"(a) : "l"(p));
    return a;
}
__device__ __forceinline__ float ex2f(float x) { float y; asm("ex2.approx.ftz.f32 %0, %1;" : "=f"(y) : "f"(x)); return y; }
__device__ __forceinline__ float rcpf(float x) { float y; asm("rcp.approx.ftz.f32 %0, %1;" : "=f"(y) : "f"(x)); return y; }
__device__ __forceinline__ float fsig(float z)  { return rcpf(1.f + ex2f(-1.44269504088896f * z)); }
__device__ __forceinline__ float ftanh(float z) { return 1.f - 2.f * rcpf(1.f + ex2f(2.88539008177793f * z)); }

__device__ __forceinline__ void cp16(void* dst, const void* src) {
    u32 d = smem_u32(dst);
    asm volatile("cp.async.cg.shared.global [%0], [%1], 16;\n" :: "r"(d), "l"(src));
}
__device__ __forceinline__ void cp_commit() { asm volatile("cp.async.commit_group;\n" ::); }
__device__ __forceinline__ void cp_wait0()  { asm volatile("cp.async.wait_group 0;\n" ::); }

#define LDM4(r0, r1, r2, r3, addr) \
    asm volatile("ldmatrix.sync.aligned.m8n8.x4.shared.b16 {%0,%1,%2,%3}, [%4];" \
        : "=r"(r0), "=r"(r1), "=r"(r2), "=r"(r3) : "r"(addr))

#define MMA4(d, A0, A1, A2, A3, B0, B1) \
    asm volatile("mma.sync.aligned.m16n8k16.row.col.f32.f16.f16.f32 " \
        "{%0,%1,%2,%3}, {%4,%5,%6,%7}, {%8,%9}, {%0,%1,%2,%3};" \
        : "+f"((d)[0]), "+f"((d)[1]), "+f"((d)[2]), "+f"((d)[3]) \
        : "r"(A0), "r"(A1), "r"(A2), "r"(A3), "r"(B0), "r"(B1))

// ---------------- grid-wide barrier (per-CTA flag slots) ----------------
__device__ __forceinline__ void grid_sync_flag(int jt, int tid, unsigned gen) {
    __syncthreads();
    if (tid == 0) {
        __threadfence();
        *((volatile unsigned*)&g_flags[jt * 32]) = gen;
    }
    if (tid < NCTA) {
        while (*((volatile unsigned*)&g_flags[tid * 32]) < gen) { }
    }
    __threadfence();
    __syncthreads();
}

// swizzled element offset inside a [rows][128k] f16 tile
__device__ __forceinline__ u32 swzoff(int row, int k) {
    return (u32)row * 256u + ((((u32)(k >> 3)) ^ ((u32)row & 7u)) << 4) + (((u32)k & 7u) << 1);
}

// ---------------- prep: f16-convert + swizzle x, W; zero h ----------------
__global__ void prep_kernel(const float* __restrict__ x,
                            const float* __restrict__ W0,
                            const float* __restrict__ W1)
{
    const int stride = gridDim.x * blockDim.x;
    const int t0 = blockIdx.x * blockDim.x + threadIdx.x;

    if (t0 < NCTA * 32) g_flags[t0] = 0u;

    for (int i = t0; i < 2 * 4 * 32768 / 4; i += stride) {
        ((u32*)g_h0s)[i] = 0u;
        ((u32*)g_h1s)[i] = 0u;
    }
    // x tiles: rows = b, cols = d-chunk
    for (int idx = t0; idx < S_ * 2 * 128 * 128; idx += stride) {
        int t   = idx / (2 * 128 * 128);
        int rem = idx % (2 * 128 * 128);
        int ch  = rem / (128 * 128);
        int b   = (rem / 128) % 128;
        int k   = rem % 128;
        float v = x[(b * S_ + t) * D_ + ch * 128 + k];
        *(__half*)(&g_xs[t][ch][swzoff(b, k)]) = __float2half_rn(v);
    }
    // W tiles: rows n = gate*8+u  ->  W col gate*512 + jt*8 + u
    for (int idx = t0; idx < NCTA * 6 * 32 * 128; idx += stride) {
        int jt  = idx / (6 * 32 * 128);
        int rem = idx % (6 * 32 * 128);
        int ch  = rem / (32 * 128);
        int n   = (rem / 128) % 32;
        int k   = rem % 128;
        float v = W0[(ch * 128 + k) * 2048 + (n >> 3) * 512 + jt * 8 + (n & 7)];
        *(__half*)(&g_W0s[jt][ch][swzoff(n, k)]) = __float2half_rn(v);
    }
    for (int idx = t0; idx < NCTA * 8 * 32 * 128; idx += stride) {
        int jt  = idx / (8 * 32 * 128);
        int rem = idx % (8 * 32 * 128);
        int ch  = rem / (32 * 128);
        int n   = (rem / 128) % 32;
        int k   = rem % 128;
        float v = W1[(ch * 128 + k) * 2048 + (n >> 3) * 512 + jt * 8 + (n & 7)];
        *(__half*)(&g_W1s[jt][ch][swzoff(n, k)]) = __float2half_rn(v);
    }
}

// ---------------- linear 32KB stage (src pre-swizzled in gmem) ----------------
__device__ __forceinline__ void stage(unsigned char* dst, const unsigned char* src, int tid) {
    #pragma unroll
    for (int i = 0; i < 8; i++) {
        int o = (tid + (i << 8)) << 4;
        cp16(dst + o, src + o);
    }
}

// ---------------- one GEMM phase: acc[M=32 cols][N=128 b] over nch K128 chunks ----
// 8 warps: warp w owns batches [16w, 16w+16). acc regs: [mi*8 + nt*4 + {0..3}].
__device__ __forceinline__ void gemm_phase(
    const unsigned char* const* tiles, int nch,
    u32 wbase, unsigned char* s_act, u32 actbase,
    float* acc, int tid, int lane, int warp)
{
    #pragma unroll
    for (int i = 0; i < 16; i++) acc[i] = 0.f;

    stage(s_act, tiles[0], tid);
    cp_commit();

    const u32 sA  = lane & 7;
    const u32 rA  = (u32)((((lane >> 3) & 1) << 3) | (lane & 7));
    const u32 kgA = (u32)(lane >> 4);
    const u32 rB  = (u32)(((lane >> 4) << 3) + (lane & 7) + warp * 16);
    const u32 kgB = (u32)((lane >> 3) & 1);

    for (int ch = 0; ch < nch; ch++) {
        cp_wait0();
        __syncthreads();
        if (ch + 1 < nch) {
            stage(s_act + (((ch + 1) & 1) << 15), tiles[ch + 1], tid);
            cp_commit();
        }
        const u32 ab  = actbase + ((u32)(ch & 1) << 15);
        const u32 wb  = wbase + ((u32)ch << 13);
        const u32 aB0 = wb + rA * 256u;
        const u32 aB1 = aB0 + 4096u;            // +16 rows
        const u32 bB  = ab + rB * 256u;
        #pragma unroll
        for (int j = 0; j < 8; j++) {
            u32 kiA = ((((u32)(2 * j)) | kgA) ^ sA) << 4;
            u32 kiB = ((((u32)(2 * j)) | kgB) ^ sA) << 4;
            u32 a0, a1, a2, a3, e0, e1, e2, e3, b0, b1, b2, b3;
            LDM4(a0, a1, a2, a3, aB0 + kiA);
            LDM4(e0, e1, e2, e3, aB1 + kiA);
            LDM4(b0, b1, b2, b3, bB + kiB);
            MMA4(acc + 0,  a0, a1, a2, a3, b0, b1);   // mi0 (gates i,f), nt0
            MMA4(acc + 4,  a0, a1, a2, a3, b2, b3);   // mi0, nt1
            MMA4(acc + 8,  e0, e1, e2, e3, b0, b1);   // mi1 (gates g,o), nt0
            MMA4(acc + 12, e0, e1, e2, e3, b2, b3);   // mi1, nt1
        }
    }
    __syncthreads();
}

// ---------------- epilogue: in-register gates, f16 h store ----------------
__device__ __forceinline__ void epilogue(
    const float* acc, float* cst, float4 bias,
    unsigned char* hdst, u32 cj, int lane, int warp, int u)
{
    #pragma unroll
    for (int nt = 0; nt < 2; nt++) {
        #pragma unroll
        for (int e = 0; e < 2; e++) {
            float zi = acc[nt * 4 + e]          + bias.x;
            float zf = acc[nt * 4 + 2 + e]      + bias.y;
            float zg = acc[8 + nt * 4 + e]      + bias.z;
            float zo = acc[8 + nt * 4 + 2 + e]  + bias.w;
            float c  = cst[nt * 2 + e];
            float cn = fsig(zf) * c + fsig(zi) * ftanh(zg);
            cst[nt * 2 + e] = cn;
            float h = fsig(zo) * ftanh(cn);
            int b = warp * 16 + nt * 8 + (lane & 3) * 2 + e;
            u32 off = (u32)b * 256u + ((cj ^ ((u32)b & 7u)) << 4) + (u32)u * 2u;
            *(__half*)(hdst + off) = __float2half_rn(h);
        }
    }
}

// ---------------- persistent main kernel: 64 CTAs x 256 threads ----------------
__global__ void __launch_bounds__(256, 1)
lstm_main(const float* __restrict__ b0g,
          const float* __restrict__ b1g,
          const float* __restrict__ Wp,
          const float* __restrict__ bp,
          float* __restrict__ out)
{
    extern __shared__ __align__(256) unsigned char smem[];
    unsigned char* s_w   = smem;             // 6*8192 + 8*8192 = 114688
    unsigned char* s_act = smem + 114688;    // 2 x 32768 = 65536
    // total 180224 bytes

    const int tid  = threadIdx.x;
    const int lane = tid & 31;
    const int warp = tid >> 5;
    const int jt   = blockIdx.x;
    const int u    = lane >> 2;              // unit 0..7 within CTA

    // preload weights (f16, pre-swizzled): 48KB + 64KB, linear cp.async
    {
        const unsigned char* w0 = &g_W0s[jt][0][0];
        const unsigned char* w1 = &g_W1s[jt][0][0];
        #pragma unroll
        for (int i = 0; i < 12; i++) { int o = (tid + (i << 8)) << 4; cp16(s_w + o, w0 + o); }
        #pragma unroll
        for (int i = 0; i < 16; i++) { int o = (tid + (i << 8)) << 4; cp16(s_w + 49152 + o, w1 + o); }
        cp_commit();
        cp_wait0();
    }
    __syncthreads();

    const int jb = jt * 8 + u;
    const float4 bias0 = make_float4(b0g[jb], b0g[512 + jb], b0g[1024 + jb], b0g[1536 + jb]);
    const float4 bias1 = make_float4(b1g[jb], b1g[512 + jb], b1g[1024 + jb], b1g[1536 + jb]);

    float c0r[4] = {0.f, 0.f, 0.f, 0.f};
    float c1r[4] = {0.f, 0.f, 0.f, 0.f};
    float acc[16];

    const u32 actbase = smem_u32(s_act);
    const u32 wb0 = smem_u32(s_w);
    const u32 wb1 = wb0 + 49152u;
    const u32 cj = (u32)((jt * 8) & 127) >> 3;
    const int htile = (jt * 8) >> 7;

    const unsigned char* tiles[8];

    for (int t = 0; t < S_; t++) {
        const int cur = t & 1, prv = cur ^ 1;

        // ---- L0: K = 768 = [x 2 chunks][h0_prev 4 chunks] ----
        tiles[0] = &g_xs[t][0][0];
        tiles[1] = &g_xs[t][1][0];
        #pragma unroll
        for (int q = 0; q < 4; q++) tiles[2 + q] = &g_h0s[prv][q][0];
        gemm_phase(tiles, 6, wb0, s_act, actbase, acc, tid, lane, warp);
        epilogue(acc, c0r, bias0, &g_h0s[cur][htile][0], cj, lane, warp, u);

        grid_sync_flag(jt, tid, (unsigned)(t + 1));   // h0(t), h1(t-1) visible

        // ---- L1: K = 1024 = [h0_cur 4][h1_prev 4] ----
        #pragma unroll
        for (int q = 0; q < 4; q++) { tiles[q] = &g_h0s[cur][q][0]; tiles[4 + q] = &g_h1s[prv][q][0]; }
        gemm_phase(tiles, 8, wb1, s_act, actbase, acc, tid, lane, warp);
        epilogue(acc, c1r, bias1, &g_h1s[cur][htile][0], cj, lane, warp, u);
        // next step's barrier orders h1(t) -> L1(t+1)
    }

    grid_sync_flag(jt, tid, (unsigned)(S_ + 1));

    // ---- projection: out[b][m] = sum_j h1[b][j] * Wp[j][m] + bp[m] ----
    {
        const unsigned char* h1b = &g_h1s[1][0][0];   // buf 1 (t = 511)
        int mstart = jt * 20;
        int mend = mstart + 20; if (mend > ODIM) mend = ODIM;
        int b  = tid & 127;
        int mq = tid >> 7;     // 0..1
        for (int m = mstart + mq; m < mend; m += 2) {
            float a = bp[m];
            for (int k = 0; k < H_; k++) {
                u32 off = swzoff(b, k & 127);
                a += __half2float(*(const __half*)(h1b + (size_t)(k >> 7) * 32768 + off))
                     * Wp[k * ODIM + m];
            }
            out[b * ODIM + m] = a;
        }
    }
}

// ---------------- entry ----------------
extern "C" void kernel_launch(void* const* d_in, const int* in_sizes, int n_in,
                              void* d_out, int out_size)
{
    const float* x  = (const float*)d_in[0];
    const float* W0 = (const float*)d_in[1];
    const float* b0 = (const float*)d_in[2];
    const float* W1 = (const float*)d_in[3];
    const float* b1 = (const float*)d_in[4];
    const float* Wp = (const float*)d_in[5];
    const float* bp = (const float*)d_in[6];
    float* out = (float*)d_out;

    cudaFuncSetAttribute(lstm_main, cudaFuncAttributeMaxDynamicSharedMemorySize, 180224);

    prep_kernel<<<2048, 256>>>(x, W0, W1);
    lstm_main<<<NCTA, 256, 180224>>>(b0, b1, Wp, bp, out);
}